// round 11
// baseline (speedup 1.0000x reference)
#include <cuda_runtime.h>

// ---------------------------------------------------------------------------
// Device scratch. Sized with margin over N=4096, D=64.
// ---------------------------------------------------------------------------
#define SCRATCH_ELEMS (1 << 20)
__device__ float g_a[SCRATCH_ELEMS];
__device__ float g_c[SCRATCH_ELEMS];

// ---------------------------------------------------------------------------
// Kernel 1: per-node projections (D=64 specialized, vectorized).
// a[i][d] = sum_k x[i][k]*W[d][k] + b[d] ;  c[i][d] = sum_k x[i][k]*W[d][64+k]
// W [64,128] staged via LDG.128 into smem, row stride 132 (16B aligned;
// 132 mod 32 = 4, so quarter-warp lanes start at word 4d mod 32 ->
// conflict-free LDS.128).
// PROJ_BN=32 nodes/block, 1024 threads -> grid = N/32 = 128 blocks:
// a SINGLE wave on 148 SMs (the kernel is wave-latency bound, not
// warp-count bound — measured R8/R10).
// ---------------------------------------------------------------------------
#define PROJ_BN 32
#define WS_STRIDE 132

__global__ __launch_bounds__(1024, 1)
void proj64_kernel(const float* __restrict__ x,
                   const float* __restrict__ W,
                   const float* __restrict__ bias,
                   int N) {
    __shared__ __align__(16) float ws[64 * WS_STRIDE];
    __shared__ __align__(16) float xs[PROJ_BN][64];

    int tid = threadIdx.x;  // 1024

    // Stage W: 2048 float4 over 1024 threads -> 2 LDG.128 each.
    const float4* __restrict__ W4 = reinterpret_cast<const float4*>(W);
#pragma unroll
    for (int i4 = tid; i4 < 64 * 32; i4 += 1024) {
        int r = i4 >> 5;
        int c4 = i4 & 31;
        *reinterpret_cast<float4*>(&ws[r * WS_STRIDE + c4 * 4]) = W4[i4];
    }

    int base = blockIdx.x * PROJ_BN;
    // Stage x tile: PROJ_BN*16 = 512 float4.
    const float4* __restrict__ x4 = reinterpret_cast<const float4*>(x);
    if (tid < PROJ_BN * 16) {
        int nd = tid >> 4, k4 = tid & 15;
        int node = base + nd;
        float4 v = (node < N) ? x4[(size_t)node * 16 + k4]
                              : make_float4(0.f, 0.f, 0.f, 0.f);
        *reinterpret_cast<float4*>(&xs[nd][k4 * 4]) = v;
    }
    __syncthreads();

    int d = tid & 63;
    int ty = tid >> 6;  // 0..15 -> nodes ty*2, ty*2+1

    const float4* __restrict__ wrowA =
        reinterpret_cast<const float4*>(&ws[d * WS_STRIDE]);
    const float4* __restrict__ wrowC =
        reinterpret_cast<const float4*>(&ws[d * WS_STRIDE + 64]);

    float accA0 = 0.f, accA1 = 0.f, accC0 = 0.f, accC1 = 0.f;

#pragma unroll
    for (int k4 = 0; k4 < 16; k4++) {
        float4 wA = wrowA[k4];
        float4 wC = wrowC[k4];
        float4 v0 = *reinterpret_cast<const float4*>(&xs[ty * 2][k4 * 4]);
        float4 v1 = *reinterpret_cast<const float4*>(&xs[ty * 2 + 1][k4 * 4]);
        accA0 = fmaf(v0.x, wA.x, accA0); accA0 = fmaf(v0.y, wA.y, accA0);
        accA0 = fmaf(v0.z, wA.z, accA0); accA0 = fmaf(v0.w, wA.w, accA0);
        accC0 = fmaf(v0.x, wC.x, accC0); accC0 = fmaf(v0.y, wC.y, accC0);
        accC0 = fmaf(v0.z, wC.z, accC0); accC0 = fmaf(v0.w, wC.w, accC0);
        accA1 = fmaf(v1.x, wA.x, accA1); accA1 = fmaf(v1.y, wA.y, accA1);
        accA1 = fmaf(v1.z, wA.z, accA1); accA1 = fmaf(v1.w, wA.w, accA1);
        accC1 = fmaf(v1.x, wC.x, accC1); accC1 = fmaf(v1.y, wC.y, accC1);
        accC1 = fmaf(v1.z, wC.z, accC1); accC1 = fmaf(v1.w, wC.w, accC1);
    }

    float bv = bias[d];
    int n0 = base + ty * 2;
    if (n0 < N) {
        g_a[(size_t)n0 * 64 + d] = accA0 + bv;
        g_c[(size_t)n0 * 64 + d] = accC0;
    }
    if (n0 + 1 < N) {
        g_a[(size_t)(n0 + 1) * 64 + d] = accA1 + bv;
        g_c[(size_t)(n0 + 1) * 64 + d] = accC1;
    }
}

// ---------------------------------------------------------------------------
// Kernel 2: dense fill, one row per block (best measured configuration).
// out[gi, j, :] = a[gi] + c[g*n + j].
// Plain (write-back) stores this round: keeps the freshly written out-lines
// L2-resident so the scatter pass's atomics RMW in L2 instead of DRAM.
// ---------------------------------------------------------------------------
__global__ void fill_kernel(float4* __restrict__ out, int n, int D4) {
    int gi = blockIdx.x;
    int g = gi / n;

    const float4* __restrict__ a4 =
        reinterpret_cast<const float4*>(g_a) + (size_t)gi * D4;
    const float4* __restrict__ cbase =
        reinterpret_cast<const float4*>(g_c) + (size_t)g * n * D4;

    int d4 = threadIdx.x % D4;
    int j0 = threadIdx.x / D4;
    int jstep = blockDim.x / D4;

    float4 av = a4[d4];
    float4* __restrict__ orow = out + (size_t)gi * n * D4;

    for (int j = j0; j < n; j += jstep) {
        float4 cv = cbase[(size_t)j * D4 + d4];
        float4 o;
        o.x = av.x + cv.x;
        o.y = av.y + cv.y;
        o.z = av.z + cv.z;
        o.w = av.w + cv.w;
        orow[(size_t)j * D4 + d4] = o;
    }
}

// ---------------------------------------------------------------------------
// Kernel 3: edge scatter-add. out[src, dst - g*n, :] += attr[e, :]
// (g*n + li == src for equal-sized graphs; g = src / n.)
// 128-bit atomicAdd (native REDG.128 on sm_90+). Indices are int32.
// ---------------------------------------------------------------------------
__global__ void scatter_kernel(const int* __restrict__ edge_index,
                               const float4* __restrict__ edge_attr,
                               float4* __restrict__ out,
                               int E, int n, int D4) {
    int t = blockIdx.x * blockDim.x + threadIdx.x;
    int e = t / D4;
    int d4 = t % D4;
    if (e >= E) return;

    int src = edge_index[e];
    int dst = edge_index[E + e];
    int g = src / n;
    int lj = dst - g * n;

    float4 v = edge_attr[(size_t)e * D4 + d4];
    atomicAdd(&out[((size_t)src * n + lj) * D4 + d4], v);
}

// ---------------------------------------------------------------------------
extern "C" void kernel_launch(void* const* d_in, const int* in_sizes, int n_in,
                              void* d_out, int out_size) {
    const float* x = (const float*)d_in[0];
    const int* edge_index = (const int*)d_in[1];
    const float* edge_attr = (const float*)d_in[2];
    // d_in[3] = batch: implied by src / n for equal-sized graphs
    // d_in[4] = token_index: unused (it enumerates all (i,j) pairs in order)
    const float* W = (const float*)d_in[5];
    const float* b = (const float*)d_in[6];

    int D = in_sizes[6];     // 64
    int N = in_sizes[3];     // 4096 nodes total
    int E = in_sizes[2] / D; // 65536 edges
    int T = in_sizes[4] / 2; // 524288 pairs
    int n = T / N;           // 128 nodes per graph
    int D4 = D / 4;          // 16 float4 per feature row

    float* out = (float*)d_out;

    // 1. per-node projections (single wave: N/32 = 128 blocks of 1024)
    {
        int grid = (N + PROJ_BN - 1) / PROJ_BN;
        proj64_kernel<<<grid, 1024>>>(x, W, b, N);
    }

    // 2. dense broadcast fill (writes the whole 128 MiB output once)
    fill_kernel<<<N, 256>>>((float4*)out, n, D4);

    // 3. edge feature scatter-add
    {
        long long work = (long long)E * D4;
        scatter_kernel<<<(int)((work + 255) / 256), 256>>>(
            edge_index, (const float4*)edge_attr, (float4*)out, E, n, D4);
    }
}

// round 12
// speedup vs baseline: 1.1099x; 1.1099x over previous
#include <cuda_runtime.h>

// ---------------------------------------------------------------------------
// Device scratch. Sized with margin over N=4096, D=64.
// ---------------------------------------------------------------------------
#define SCRATCH_ELEMS (1 << 20)
__device__ float g_a[SCRATCH_ELEMS];
__device__ float g_c[SCRATCH_ELEMS];

// ---------------------------------------------------------------------------
// Kernel 1: per-node projections (R8 configuration — best measured: 7.9us).
// a[i][d] = sum_k x[i][k]*W[d][k] + b[d] ;  c[i][d] = sum_k x[i][k]*W[d][64+k]
// W [64,128] staged via LDG.128 into smem, row stride 132 (16B aligned,
// conflict-free LDS.128). PROJ_BN=16 nodes/block, 256 threads, 4 nodes/thread.
// ---------------------------------------------------------------------------
#define PROJ_BN 16
#define WS_STRIDE 132

__global__ void proj64_kernel(const float* __restrict__ x,
                              const float* __restrict__ W,
                              const float* __restrict__ bias,
                              int N) {
    __shared__ __align__(16) float ws[64 * WS_STRIDE];
    __shared__ __align__(16) float xs[PROJ_BN][64];

    int tid = threadIdx.x;  // 256

    // Stage W: 2048 float4 over 256 threads -> 8 LDG.128 each.
    const float4* __restrict__ W4 = reinterpret_cast<const float4*>(W);
#pragma unroll
    for (int i4 = tid; i4 < 64 * 32; i4 += 256) {
        int r = i4 >> 5;
        int c4 = i4 & 31;
        *reinterpret_cast<float4*>(&ws[r * WS_STRIDE + c4 * 4]) = W4[i4];
    }

    int base = blockIdx.x * PROJ_BN;
    // Stage x tile: PROJ_BN*16 = 256 float4 -> 1 per thread.
    const float4* __restrict__ x4 = reinterpret_cast<const float4*>(x);
#pragma unroll
    for (int i4 = tid; i4 < PROJ_BN * 16; i4 += 256) {
        int nd = i4 >> 4, k4 = i4 & 15;
        int node = base + nd;
        float4 v = (node < N) ? x4[(size_t)node * 16 + k4]
                              : make_float4(0.f, 0.f, 0.f, 0.f);
        *reinterpret_cast<float4*>(&xs[nd][k4 * 4]) = v;
    }
    __syncthreads();

    int d = tid & 63;
    int ty = tid >> 6;  // 0..3 -> nodes ty*4 .. ty*4+3

    const float4* __restrict__ wrowA =
        reinterpret_cast<const float4*>(&ws[d * WS_STRIDE]);
    const float4* __restrict__ wrowC =
        reinterpret_cast<const float4*>(&ws[d * WS_STRIDE + 64]);

    float accA[4] = {0.f, 0.f, 0.f, 0.f};
    float accC[4] = {0.f, 0.f, 0.f, 0.f};

#pragma unroll
    for (int k4 = 0; k4 < 16; k4++) {
        float4 wA = wrowA[k4];
        float4 wC = wrowC[k4];
#pragma unroll
        for (int u = 0; u < 4; u++) {
            float4 v = *reinterpret_cast<const float4*>(&xs[ty * 4 + u][k4 * 4]);
            accA[u] = fmaf(v.x, wA.x, accA[u]); accA[u] = fmaf(v.y, wA.y, accA[u]);
            accA[u] = fmaf(v.z, wA.z, accA[u]); accA[u] = fmaf(v.w, wA.w, accA[u]);
            accC[u] = fmaf(v.x, wC.x, accC[u]); accC[u] = fmaf(v.y, wC.y, accC[u]);
            accC[u] = fmaf(v.z, wC.z, accC[u]); accC[u] = fmaf(v.w, wC.w, accC[u]);
        }
    }

    float bv = bias[d];
#pragma unroll
    for (int u = 0; u < 4; u++) {
        int node = base + ty * 4 + u;
        if (node < N) {
            g_a[(size_t)node * 64 + d] = accA[u] + bv;
            g_c[(size_t)node * 64 + d] = accC[u];
        }
    }
}

// ---------------------------------------------------------------------------
// Kernel 2: dense fill, 4 rows per block via PARALLEL 128-thread groups
// (no serial row loop). All 4 groups stream the same graph's c row-set
// concurrently -> L1/MSHR merges the reads, cutting the c L2 re-read 4x.
// out[gi, j, :] = a[gi] + c[g*n + j].  __stcs streaming stores (proven -4us).
// Requires D4 == 16 and n % 4 == 0 (else fill1 fallback).
// ---------------------------------------------------------------------------
__global__ void fill4_kernel(float4* __restrict__ out, int n) {
    const int D4 = 16;
    int group = threadIdx.x >> 7;     // 0..3 -> row
    int t = threadIdx.x & 127;
    int gi = blockIdx.x * 4 + group;
    int g = gi / n;

    const float4* __restrict__ a4 =
        reinterpret_cast<const float4*>(g_a) + (size_t)gi * D4;
    const float4* __restrict__ cbase =
        reinterpret_cast<const float4*>(g_c) + (size_t)g * n * D4;

    int d4 = t & 15;      // 0..15
    int j0 = t >> 4;      // 0..7
    float4 av = a4[d4];
    float4* __restrict__ orow = out + (size_t)gi * n * D4;

    for (int j = j0; j < n; j += 8) {
        float4 cv = cbase[(size_t)j * D4 + d4];
        float4 o;
        o.x = av.x + cv.x;
        o.y = av.y + cv.y;
        o.z = av.z + cv.z;
        o.w = av.w + cv.w;
        __stcs(&orow[(size_t)j * D4 + d4], o);
    }
}

// Generic fallback: one row per block.
__global__ void fill1_kernel(float4* __restrict__ out, int n, int D4) {
    int gi = blockIdx.x;
    int g = gi / n;
    const float4* __restrict__ a4 =
        reinterpret_cast<const float4*>(g_a) + (size_t)gi * D4;
    const float4* __restrict__ cbase =
        reinterpret_cast<const float4*>(g_c) + (size_t)g * n * D4;
    int d4 = threadIdx.x % D4;
    int j0 = threadIdx.x / D4;
    int jstep = blockDim.x / D4;
    float4 av = a4[d4];
    float4* __restrict__ orow = out + (size_t)gi * n * D4;
    for (int j = j0; j < n; j += jstep) {
        float4 cv = cbase[(size_t)j * D4 + d4];
        float4 o;
        o.x = av.x + cv.x;
        o.y = av.y + cv.y;
        o.z = av.z + cv.z;
        o.w = av.w + cv.w;
        __stcs(&orow[(size_t)j * D4 + d4], o);
    }
}

// ---------------------------------------------------------------------------
// Kernel 3: edge scatter-add. out[src, dst - g*n, :] += attr[e, :]
// (g*n + li == src for equal-sized graphs; g = src / n.)
// 128-bit atomicAdd (native REDG.128 on sm_90+). Indices are int32.
// ---------------------------------------------------------------------------
__global__ void scatter_kernel(const int* __restrict__ edge_index,
                               const float4* __restrict__ edge_attr,
                               float4* __restrict__ out,
                               int E, int n, int D4) {
    int t = blockIdx.x * blockDim.x + threadIdx.x;
    int e = t / D4;
    int d4 = t % D4;
    if (e >= E) return;

    int src = edge_index[e];
    int dst = edge_index[E + e];
    int g = src / n;
    int lj = dst - g * n;

    float4 v = edge_attr[(size_t)e * D4 + d4];
    atomicAdd(&out[((size_t)src * n + lj) * D4 + d4], v);
}

// ---------------------------------------------------------------------------
extern "C" void kernel_launch(void* const* d_in, const int* in_sizes, int n_in,
                              void* d_out, int out_size) {
    const float* x = (const float*)d_in[0];
    const int* edge_index = (const int*)d_in[1];
    const float* edge_attr = (const float*)d_in[2];
    // d_in[3] = batch: implied by src / n for equal-sized graphs
    // d_in[4] = token_index: unused (it enumerates all (i,j) pairs in order)
    const float* W = (const float*)d_in[5];
    const float* b = (const float*)d_in[6];

    int D = in_sizes[6];     // 64
    int N = in_sizes[3];     // 4096 nodes total
    int E = in_sizes[2] / D; // 65536 edges
    int T = in_sizes[4] / 2; // 524288 pairs
    int n = T / N;           // 128 nodes per graph
    int D4 = D / 4;          // 16 float4 per feature row

    float* out = (float*)d_out;

    // 1. per-node projections
    {
        int grid = (N + PROJ_BN - 1) / PROJ_BN;
        proj64_kernel<<<grid, 256>>>(x, W, b, N);
    }

    // 2. dense broadcast fill (writes the whole 128 MiB output once)
    if (D4 == 16 && n % 4 == 0 && N % 4 == 0)
        fill4_kernel<<<N / 4, 512>>>((float4*)out, n);
    else
        fill1_kernel<<<N, 256>>>((float4*)out, n, D4);

    // 3. edge feature scatter-add
    {
        long long work = (long long)E * D4;
        scatter_kernel<<<(int)((work + 255) / 256), 256>>>(
            edge_index, (const float4*)edge_attr, (float4*)out, E, n, D4);
    }
}